// round 4
// baseline (speedup 1.0000x reference)
#include <cuda_runtime.h>
#include <cstdint>
#include <mma.h>

using namespace nvcuda;

#define BATCH 16
#define C_IN 384
#define C_HID 1536
#define HW 1024
#define EMB_D 1024
#define N_GROUPS 32
#define C_PER_G 12
#define GN_EPS 1e-5f

// Scratch (device globals; no allocations allowed)
__device__ float g_h[BATCH * C_HID * HW];   // 100 MB hidden activations
__device__ float g_xn[BATCH * C_IN * HW];   // 25 MB normalized input
__device__ float g_na[BATCH * C_IN];
__device__ float g_nb[BATCH * C_IN];
__device__ float g_scale[BATCH * C_HID];
__device__ float g_shift[BATCH * C_HID];

// ---------------------------------------------------------------------------
// cp.async helpers
// ---------------------------------------------------------------------------
__device__ __forceinline__ void cp16(uint32_t dst, const void* src) {
    asm volatile("cp.async.cg.shared.global [%0], [%1], 16;\n" :: "r"(dst), "l"(src));
}
__device__ __forceinline__ void cp_commit() {
    asm volatile("cp.async.commit_group;\n");
}
template <int N>
__device__ __forceinline__ void cp_wait() {
    asm volatile("cp.async.wait_group %0;\n" :: "n"(N));
}

// ---------------------------------------------------------------------------
// K1: GroupNorm statistics -> per-(b,c) affine: xn = x * g_na + g_nb
// ---------------------------------------------------------------------------
__global__ void gn_stats_kernel(const float* __restrict__ x,
                                const float* __restrict__ gw,
                                const float* __restrict__ gb) {
    int b = blockIdx.x >> 5;
    int g = blockIdx.x & 31;
    const float4* p = (const float4*)(x + ((size_t)(b * C_IN + g * C_PER_G)) * HW);

    float s = 0.f, q = 0.f;
    for (int i = threadIdx.x; i < (C_PER_G * HW) / 4; i += 256) {
        float4 v = p[i];
        s += v.x + v.y + v.z + v.w;
        q += v.x * v.x + v.y * v.y + v.z * v.z + v.w * v.w;
    }
    __shared__ float ss[256], sq[256];
    ss[threadIdx.x] = s; sq[threadIdx.x] = q;
    __syncthreads();
    for (int o = 128; o; o >>= 1) {
        if (threadIdx.x < o) {
            ss[threadIdx.x] += ss[threadIdx.x + o];
            sq[threadIdx.x] += sq[threadIdx.x + o];
        }
        __syncthreads();
    }
    __shared__ float smu, srs;
    if (threadIdx.x == 0) {
        const float inv_n = 1.f / (float)(C_PER_G * HW);
        float mu = ss[0] * inv_n;
        float var = sq[0] * inv_n - mu * mu;
        smu = mu;
        srs = rsqrtf(var + GN_EPS);
    }
    __syncthreads();
    if (threadIdx.x < C_PER_G) {
        int c = g * C_PER_G + threadIdx.x;
        float a = srs * gw[c];
        g_na[b * C_IN + c] = a;
        g_nb[b * C_IN + c] = gb[c] - smu * a;
    }
}

// ---------------------------------------------------------------------------
// K2: emb_out = emb @ we^T + be -> g_scale / g_shift
// ---------------------------------------------------------------------------
__global__ void emb_gemm_kernel(const float* __restrict__ emb,
                                const float* __restrict__ we,
                                const float* __restrict__ be) {
    int w = (blockIdx.x * blockDim.x + threadIdx.x) >> 5;
    int lane = threadIdx.x & 31;
    if (w >= 2 * C_HID) return;

    const float4* wr = (const float4*)(we + (size_t)w * EMB_D);
    float4 wv[8];
#pragma unroll
    for (int i = 0; i < 8; i++) wv[i] = wr[i * 32 + lane];
    float bias = be[w];

    for (int b = 0; b < BATCH; b++) {
        const float4* er = (const float4*)(emb + (size_t)b * EMB_D);
        float d = 0.f;
#pragma unroll
        for (int i = 0; i < 8; i++) {
            float4 e = er[i * 32 + lane];
            d += wv[i].x * e.x + wv[i].y * e.y + wv[i].z * e.z + wv[i].w * e.w;
        }
#pragma unroll
        for (int o = 16; o; o >>= 1) d += __shfl_xor_sync(0xffffffffu, d, o);
        if (lane == 0) {
            float v = d + bias;
            if (w < C_HID) g_scale[b * C_HID + w] = v;
            else           g_shift[b * C_HID + (w - C_HID)] = v;
        }
    }
}

// ---------------------------------------------------------------------------
// K3: g_xn = x * na + nb  (GroupNorm applied, so GEMM1 can cp.async raw)
// ---------------------------------------------------------------------------
__global__ void gn_apply_kernel(const float* __restrict__ x) {
    size_t i4 = (size_t)blockIdx.x * blockDim.x + threadIdx.x;
    float4 v = ((const float4*)x)[i4];
    int row = (int)(i4 >> 8);           // b*C_IN + c  (HW/4 = 256)
    float a = g_na[row], bb = g_nb[row];
    v.x = v.x * a + bb; v.y = v.y * a + bb;
    v.z = v.z * a + bb; v.w = v.w * a + bb;
    ((float4*)g_xn)[i4] = v;
}

// ---------------------------------------------------------------------------
// TF32 WMMA GEMM with 3-stage cp.async pipeline + fused epilogue.
//   C[b] = A(M x K) @ B[b](K x 1024), block tile 128x128x32, 8 warps.
//   EPI == 1: out = silu(acc + bias[m]) * (1 + scale[b,m]) + shift[b,m]
//   EPI == 2: out = acc + bias[m] + xres[b,m,n]   (residual)
// SMEM stage: A 128x36, B 32x132 (pads keep 16B alignment + dodge conflicts).
// Epilogue reuses pipeline SMEM as 128x132 staging tile.
// ---------------------------------------------------------------------------
#define LDA_S 36
#define LDB_S 132
#define STAGE_FLOATS (128 * LDA_S + 32 * LDB_S)   // 8832
#define NSTAGE 3
#define LDC_S 132

template <int KTOT, int EPI>
__global__ void __launch_bounds__(256)
gemm_tc_kernel(const float* __restrict__ A,
               const float* __restrict__ Bsrc,
               float* __restrict__ Cdst,
               const float* __restrict__ bias,
               const float* __restrict__ xres) {
    extern __shared__ float smem[];

    const int b = blockIdx.z;
    const int m0 = blockIdx.y * 128;
    const int n0 = blockIdx.x * 128;
    const int Mtot = gridDim.y * 128;

    const float* Bg = Bsrc + (size_t)b * KTOT * HW;
    float* Cg = Cdst + (size_t)b * Mtot * HW;

    const int tid = threadIdx.x;
    const int warp = tid >> 5;
    const int wm = warp >> 2;
    const int wn = warp & 3;

    const uint32_t smem_u = (uint32_t)__cvta_generic_to_shared(smem);

    auto issue = [&](int it, int buf) {
        uint32_t as_u = smem_u + buf * (STAGE_FLOATS * 4);
        uint32_t bs_u = as_u + 128 * LDA_S * 4;
#pragma unroll
        for (int i = 0; i < 4; i++) {
            int f = tid + i * 256;
            int r = f >> 3, c4 = (f & 7) * 4;
            cp16(as_u + (r * LDA_S + c4) * 4,
                 A + (size_t)(m0 + r) * KTOT + it * 32 + c4);
        }
#pragma unroll
        for (int i = 0; i < 4; i++) {
            int f = tid + i * 256;
            int r = f >> 5, c4 = (f & 31) * 4;
            cp16(bs_u + (r * LDB_S + c4) * 4,
                 Bg + (size_t)(it * 32 + r) * HW + n0 + c4);
        }
    };

    wmma::fragment<wmma::accumulator, 16, 16, 8, float> acc[4][2];
#pragma unroll
    for (int i = 0; i < 4; i++)
#pragma unroll
        for (int j = 0; j < 2; j++)
            wmma::fill_fragment(acc[i][j], 0.f);

    constexpr int NT = KTOT / 32;

    issue(0, 0); cp_commit();
    issue(1, 1); cp_commit();

    for (int i = 0; i < NT; i++) {
        if (i + 2 < NT) {
            issue(i + 2, (i + 2) % NSTAGE); cp_commit();
            cp_wait<2>();
        } else if (i + 1 < NT) {
            cp_wait<1>();
        } else {
            cp_wait<0>();
        }
        __syncthreads();

        float* As = smem + (i % NSTAGE) * STAGE_FLOATS;
        float* Bs = As + 128 * LDA_S;
#pragma unroll
        for (int kk = 0; kk < 4; kk++) {
            wmma::fragment<wmma::matrix_a, 16, 16, 8, wmma::precision::tf32, wmma::row_major> af[4];
            wmma::fragment<wmma::matrix_b, 16, 16, 8, wmma::precision::tf32, wmma::row_major> bf[2];
#pragma unroll
            for (int ii = 0; ii < 4; ii++)
                wmma::load_matrix_sync(af[ii], &As[(wm * 64 + ii * 16) * LDA_S + kk * 8], LDA_S);
#pragma unroll
            for (int j = 0; j < 2; j++)
                wmma::load_matrix_sync(bf[j], &Bs[(kk * 8) * LDB_S + wn * 32 + j * 16], LDB_S);
#pragma unroll
            for (int ii = 0; ii < 4; ii++)
#pragma unroll
                for (int j = 0; j < 2; j++)
                    wmma::mma_sync(acc[ii][j], af[ii], bf[j], acc[ii][j]);
        }
        __syncthreads();
    }

    // -------- Epilogue: stage accumulators through SMEM, apply fused op ----
    float* Cs = smem;   // 128 x LDC_S floats (16896 <= 3*8832)
#pragma unroll
    for (int i = 0; i < 4; i++)
#pragma unroll
        for (int j = 0; j < 2; j++)
            wmma::store_matrix_sync(&Cs[(wm * 64 + i * 16) * LDC_S + wn * 32 + j * 16],
                                    acc[i][j], LDC_S, wmma::mem_row_major);
    __syncthreads();

#pragma unroll
    for (int it = 0; it < 16; it++) {
        int f = tid + it * 256;
        int r = f >> 5;               // 0..127
        int c4 = (f & 31) * 4;        // 0..124
        int m = m0 + r;
        float4 v = *(float4*)&Cs[r * LDC_S + c4];
        if (EPI == 1) {
            float bb = bias[m];
            float sc = 1.f + g_scale[b * C_HID + m];
            float sh = g_shift[b * C_HID + m];
            float t;
            t = v.x + bb; t = t / (1.f + __expf(-t)); v.x = t * sc + sh;
            t = v.y + bb; t = t / (1.f + __expf(-t)); v.y = t * sc + sh;
            t = v.z + bb; t = t / (1.f + __expf(-t)); v.z = t * sc + sh;
            t = v.w + bb; t = t / (1.f + __expf(-t)); v.w = t * sc + sh;
        } else {
            float bb = bias[m];
            float4 xv = *(const float4*)(xres + (size_t)b * Mtot * HW + (size_t)m * HW + n0 + c4);
            v.x += bb + xv.x; v.y += bb + xv.y;
            v.z += bb + xv.z; v.w += bb + xv.w;
        }
        *(float4*)(Cg + (size_t)m * HW + n0 + c4) = v;
    }
}

// ---------------------------------------------------------------------------
extern "C" void kernel_launch(void* const* d_in, const int* in_sizes, int n_in,
                              void* d_out, int out_size) {
    const float* x    = (const float*)d_in[0];
    const float* emb  = (const float*)d_in[1];
    const float* gn_w = (const float*)d_in[2];
    const float* gn_b = (const float*)d_in[3];
    const float* w1   = (const float*)d_in[4];
    const float* b1   = (const float*)d_in[5];
    const float* we   = (const float*)d_in[6];
    const float* be   = (const float*)d_in[7];
    const float* w2   = (const float*)d_in[8];
    const float* b2   = (const float*)d_in[9];
    float* out = (float*)d_out;

    float* h_ptr;
    float* xn_ptr;
    cudaGetSymbolAddress((void**)&h_ptr, g_h);
    cudaGetSymbolAddress((void**)&xn_ptr, g_xn);

    const int smem_bytes = NSTAGE * STAGE_FLOATS * 4;   // 105984
    cudaFuncSetAttribute(gemm_tc_kernel<C_IN, 1>,
                         cudaFuncAttributeMaxDynamicSharedMemorySize, smem_bytes);
    cudaFuncSetAttribute(gemm_tc_kernel<C_HID, 2>,
                         cudaFuncAttributeMaxDynamicSharedMemorySize, smem_bytes);

    // K1: GroupNorm stats
    gn_stats_kernel<<<BATCH * N_GROUPS, 256>>>(x, gn_w, gn_b);
    // K2: FiLM parameters
    emb_gemm_kernel<<<(2 * C_HID) / 8, 256>>>(emb, we, be);
    // K3: apply GN affine -> g_xn
    gn_apply_kernel<<<(BATCH * C_IN * HW) / (4 * 256), 256>>>(x);
    // K4: h = silu(W1 @ xn + b1) * (1+scale) + shift    (fused epilogue)
    gemm_tc_kernel<C_IN, 1>
        <<<dim3(HW / 128, C_HID / 128, BATCH), 256, smem_bytes>>>(
            w1, xn_ptr, h_ptr, b1, nullptr);
    // K5: out = x + (W2 @ h + b2)                        (fused epilogue)
    gemm_tc_kernel<C_HID, 2>
        <<<dim3(HW / 128, C_IN / 128, BATCH), 256, smem_bytes>>>(
            w2, h_ptr, out, b2, x);
}